// round 16
// baseline (speedup 1.0000x reference)
#include <cuda_runtime.h>

// Problem constants
#define BB 4
#define NN 4096
#define DD 2048
#define EE 8
#define KK 1024
#define RR 128

typedef unsigned long long ull;

// ---------------- device scratch (no allocations allowed) ----------------
__device__ float d_logits[BB * EE * NN];                 // [B,E,N] gate logits
__device__ int   d_idx[BB * EE * KK];                    // selected token indices
__device__ float d_g[BB * EE * KK];                      // gate values for selected
__device__ float d_H[(size_t)BB * EE * KK * RR];         // relu(down) activations

// ---------------- f32x2 helpers (FFMA2 path, PTX-only) ----------------
__device__ __forceinline__ ull pack2(float lo, float hi) {
    ull r;
    asm("mov.b64 %0, {%1, %2};" : "=l"(r) : "f"(lo), "f"(hi));
    return r;
}
__device__ __forceinline__ void unpack2(ull v, float& lo, float& hi) {
    asm("mov.b64 {%0, %1}, %2;" : "=f"(lo), "=f"(hi) : "l"(v));
}
__device__ __forceinline__ ull ffma2(ull a, ull b, ull c) {
    ull d;
    asm("fma.rn.f32x2 %0, %1, %2, %3;" : "=l"(d) : "l"(a), "l"(b), "l"(c));
    return d;
}
__device__ __forceinline__ void red_add_v2(float* p, float a, float b) {
    asm volatile("red.global.add.v2.f32 [%0], {%1, %2};"
                 :: "l"(p), "f"(a), "f"(b) : "memory");
}

// ---------------- 1. gating: logitsT[b,e,n] = x[b,n,:] @ Wg[:,e] + bg[e] ----------------
__global__ __launch_bounds__(256) void gate_kernel(const float* __restrict__ x,
                                                   const float* __restrict__ Wg,
                                                   const float* __restrict__ bg) {
    int gw   = (blockIdx.x * 256 + threadIdx.x) >> 5;   // token id in [0, B*N)
    int lane = threadIdx.x & 31;
    const float4* xr = (const float4*)(x + (size_t)gw * DD);

    float acc[EE];
#pragma unroll
    for (int e = 0; e < EE; e++) acc[e] = 0.f;

#pragma unroll 4
    for (int it = 0; it < DD / 128; ++it) {
        float4 xv = xr[it * 32 + lane];
        int d0 = (it * 32 + lane) * 4;
        const float4* wg4 = (const float4*)(Wg + (size_t)d0 * EE);
        float xs[4] = {xv.x, xv.y, xv.z, xv.w};
#pragma unroll
        for (int j = 0; j < 4; j++) {
            float4 w0 = wg4[2 * j];
            float4 w1 = wg4[2 * j + 1];
            acc[0] += xs[j] * w0.x; acc[1] += xs[j] * w0.y;
            acc[2] += xs[j] * w0.z; acc[3] += xs[j] * w0.w;
            acc[4] += xs[j] * w1.x; acc[5] += xs[j] * w1.y;
            acc[6] += xs[j] * w1.z; acc[7] += xs[j] * w1.w;
        }
    }
#pragma unroll
    for (int off = 16; off; off >>= 1) {
#pragma unroll
        for (int e = 0; e < EE; e++)
            acc[e] += __shfl_xor_sync(0xFFFFFFFFu, acc[e], off);
    }
    if (lane < EE) {
        float v = acc[0];
#pragma unroll
        for (int e = 1; e < EE; e++) if (lane == e) v = acc[e];
        int b = gw / NN, n = gw % NN;
        d_logits[(size_t)(b * EE + lane) * NN + n] = v + bg[lane];
    }
}

// ---------------- 2. top-K per (b,e): radix select on monotone uint keys ----------------
__global__ __launch_bounds__(256) void topk_kernel() {
    const int be = blockIdx.x;                     // 0..31
    __shared__ unsigned keys[NN];
    __shared__ unsigned hist[256];
    __shared__ unsigned sh_prefix, sh_remaining, sh_cnt;

    const float* lrow = d_logits + (size_t)be * NN;
    const int tid = threadIdx.x;

    for (int i = tid; i < NN; i += 256) {
        unsigned b = __float_as_uint(lrow[i]);
        keys[i] = (b & 0x80000000u) ? ~b : (b | 0x80000000u);
    }
    if (tid == 0) { sh_prefix = 0u; sh_remaining = KK; sh_cnt = 0u; }
    __syncthreads();

    for (int pass = 0; pass < 4; ++pass) {
        int shift = 24 - 8 * pass;
        for (int i = tid; i < 256; i += 256) hist[i] = 0u;
        __syncthreads();
        unsigned prefix = sh_prefix;
        unsigned remaining = sh_remaining;
        int hs = shift + 8;
        for (int i = tid; i < NN; i += 256) {
            unsigned key = keys[i];
            bool ok = (pass == 0) || ((key >> hs) == (prefix >> hs));
            if (ok) atomicAdd(&hist[(key >> shift) & 0xFFu], 1u);
        }
        __syncthreads();
        if (tid == 0) {
            unsigned cum = 0; int sel = 0;
            for (int v = 255; v >= 0; v--) {
                if (cum + hist[v] >= remaining) { sel = v; break; }
                cum += hist[v];
            }
            sh_prefix = prefix | ((unsigned)sel << shift);
            sh_remaining = remaining - cum;
        }
        __syncthreads();
    }

    unsigned T = sh_prefix;
    unsigned eqNeed = sh_remaining;

    // strictly-greater keys take arbitrary slots (scatter-add makes order irrelevant)
    for (int i = tid; i < NN; i += 256) {
        if (keys[i] > T) {
            unsigned p = atomicAdd(&sh_cnt, 1u);
            d_idx[be * KK + p] = i;
            d_g[be * KK + p]   = lrow[i];
        }
    }
    __syncthreads();
    // ties at the threshold: lowest indices first (matches jax stable top_k)
    if (tid == 0) {
        unsigned base = sh_cnt, taken = 0;
        for (int i = 0; i < NN && taken < eqNeed; i++) {
            if (keys[i] == T) {
                d_idx[be * KK + base + taken] = i;
                d_g[be * KK + base + taken]   = lrow[i];
                taken++;
            }
        }
    }
}

// ---------------- 3. out = residual ----------------
__global__ __launch_bounds__(256) void copy_kernel(const float* __restrict__ res,
                                                   float* __restrict__ out) {
    int i = blockIdx.x * 256 + threadIdx.x;     // float4 index
    ((float4*)out)[i] = ((const float4*)res)[i];
}

// ---------------- 4. down: H = relu(gather(x) @ Wd[e] + bd[e]) ----------------
// tile: 64 tokens x 128 (all of R), K-chunks of 32 over D. 256 thr, 4x4 f32x2 accs.
__global__ __launch_bounds__(256) void down_kernel(const float* __restrict__ x,
                                                   const float* __restrict__ Wd,
                                                   const float* __restrict__ bd) {
    const int mt = blockIdx.x;          // 0..15 token tile
    const int be = blockIdx.y;          // 0..31
    const int b = be >> 3, e = be & 7;

    __shared__ float Xs[64][36];        // [m][k], padded to keep 16B alignment
    __shared__ float Ws[32][128];       // [k][r]
    __shared__ int   tok[64];

    const int tid = threadIdx.x;
    if (tid < 64) tok[tid] = d_idx[be * KK + mt * 64 + tid];
    __syncthreads();

    const int tx = tid & 15, ty = tid >> 4;
    ull acc[4][4];
#pragma unroll
    for (int r = 0; r < 4; r++)
#pragma unroll
        for (int j = 0; j < 4; j++) acc[r][j] = 0ULL;

    const float* Wdp = Wd + (size_t)e * DD * RR;
    const int lr = tid >> 3;            // 0..31
    const int lc = (tid & 7) * 4;       // 0..28
    const float* xrow0 = x + ((size_t)(b * NN + tok[lr]) * DD + lc);
    const float* xrow1 = x + ((size_t)(b * NN + tok[lr + 32]) * DD + lc);

    for (int k0 = 0; k0 < DD; k0 += 32) {
        *(float4*)&Xs[lr][lc]      = *(const float4*)(xrow0 + k0);
        *(float4*)&Xs[lr + 32][lc] = *(const float4*)(xrow1 + k0);
        const float4* wsrc = (const float4*)(Wdp + (size_t)k0 * RR);
#pragma unroll
        for (int j = 0; j < 4; j++) {
            int f = tid + j * 256;
            ((float4*)Ws)[f] = wsrc[f];
        }
        __syncthreads();
#pragma unroll
        for (int k = 0; k < 32; k++) {
            ull a[4], wv[4];
#pragma unroll
            for (int r = 0; r < 4; r++) {
                float xv = Xs[ty * 4 + r][k];
                a[r] = pack2(xv, xv);
            }
#pragma unroll
            for (int j = 0; j < 4; j++)
                wv[j] = *(const ull*)&Ws[k][tx * 2 + 32 * j];
#pragma unroll
            for (int r = 0; r < 4; r++)
#pragma unroll
                for (int j = 0; j < 4; j++)
                    acc[r][j] = ffma2(a[r], wv[j], acc[r][j]);
        }
        __syncthreads();
    }

#pragma unroll
    for (int r = 0; r < 4; r++) {
        int slot = be * KK + mt * 64 + ty * 4 + r;
        float* hrow = d_H + (size_t)slot * RR;
#pragma unroll
        for (int j = 0; j < 4; j++) {
            int col = tx * 2 + 32 * j;
            float lo, hi; unpack2(acc[r][j], lo, hi);
            lo = fmaxf(lo + bd[e * RR + col], 0.f);
            hi = fmaxf(hi + bd[e * RR + col + 1], 0.f);
            *(float2*)(hrow + col) = make_float2(lo, hi);
        }
    }
}

// ---------------- 5. up + combine: out += g * (H @ Wu[e] + bu[e] + x_in) ----------------
// grid: (D/128 chunks, K/64 token tiles, B*E). One-shot smem load, 128 k-iters.
#define UP_SMEM_BYTES ((64 * 132 + 128 * 128 + 64 + 64) * 4)
__global__ __launch_bounds__(256) void up_kernel(const float* __restrict__ x,
                                                 const float* __restrict__ Wu,
                                                 const float* __restrict__ bu,
                                                 float* __restrict__ out) {
    extern __shared__ float sm[];
    float* Hs  = sm;                       // [64][132] (padded: banks)
    float* Ws  = sm + 64 * 132;            // [128][128]
    int*   tok = (int*)(Ws + 128 * 128);   // [64]
    float* gv  = (float*)(tok + 64);       // [64]

    const int dc = blockIdx.x, mt = blockIdx.y, be = blockIdx.z;
    const int b = be >> 3, e = be & 7;
    const int tid = threadIdx.x;
    const int tx = tid & 15, ty = tid >> 4;

    if (tid < 64) {
        tok[tid] = d_idx[be * KK + mt * 64 + tid];
        gv[tid]  = d_g[be * KK + mt * 64 + tid];
    }
    {   // load H tile [64][128]
        int r = tid >> 2;
        int c = (tid & 3) * 32;
        const float4* src = (const float4*)(d_H + ((size_t)(be * KK + mt * 64 + r) * RR + c));
        float4* dst = (float4*)&Hs[r * 132 + c];
#pragma unroll
        for (int j = 0; j < 8; j++) dst[j] = src[j];
    }
    {   // load Wu chunk [128][128]
        const float* wp = Wu + ((size_t)e * RR * DD + dc * 128);
#pragma unroll
        for (int j = 0; j < 16; j++) {
            int f = tid + j * 256;
            int kk = f >> 5, c4 = (f & 31) * 4;
            *(float4*)&Ws[kk * 128 + c4] = *(const float4*)(wp + (size_t)kk * DD + c4);
        }
    }
    __syncthreads();

    ull acc[4][4];
#pragma unroll
    for (int r = 0; r < 4; r++)
#pragma unroll
        for (int j = 0; j < 4; j++) acc[r][j] = 0ULL;

#pragma unroll 8
    for (int k = 0; k < RR; k++) {
        ull a[4], wv[4];
#pragma unroll
        for (int r = 0; r < 4; r++) {
            float hv = Hs[(ty * 4 + r) * 132 + k];
            a[r] = pack2(hv, hv);
        }
#pragma unroll
        for (int j = 0; j < 4; j++)
            wv[j] = *(const ull*)&Ws[k * 128 + tx * 2 + 32 * j];
#pragma unroll
        for (int r = 0; r < 4; r++)
#pragma unroll
            for (int j = 0; j < 4; j++)
                acc[r][j] = ffma2(a[r], wv[j], acc[r][j]);
    }

    const float* bue = bu + e * DD + dc * 128;
#pragma unroll
    for (int r = 0; r < 4; r++) {
        int rl = ty * 4 + r;
        int t  = tok[rl];
        float gg = gv[rl];
        float* orow       = out + ((size_t)(b * NN + t) * DD + dc * 128);
        const float* xrow = x   + ((size_t)(b * NN + t) * DD + dc * 128);
#pragma unroll
        for (int j = 0; j < 4; j++) {
            int col = tx * 2 + 32 * j;
            float lo, hi; unpack2(acc[r][j], lo, hi);
            float2 xin = *(const float2*)(xrow + col);
            lo = gg * (lo + bue[col]     + xin.x);
            hi = gg * (hi + bue[col + 1] + xin.y);
            red_add_v2(orow + col, lo, hi);
        }
    }
}

// ---------------- launch ----------------
extern "C" void kernel_launch(void* const* d_in, const int* in_sizes, int n_in,
                              void* d_out, int out_size) {
    const float* x        = (const float*)d_in[0];
    const float* residual = (const float*)d_in[1];
    const float* Wg       = (const float*)d_in[2];
    const float* bg       = (const float*)d_in[3];
    const float* Wd       = (const float*)d_in[4];
    const float* bd       = (const float*)d_in[5];
    const float* Wu       = (const float*)d_in[6];
    const float* bu       = (const float*)d_in[7];
    float* out = (float*)d_out;

    (void)in_sizes; (void)n_in; (void)out_size;

    cudaFuncSetAttribute(up_kernel, cudaFuncAttributeMaxDynamicSharedMemorySize,
                         UP_SMEM_BYTES);

    // 1. gating logits
    gate_kernel<<<(BB * NN) / 8, 256>>>(x, Wg, bg);
    // 2. top-K selection per (b,e)
    topk_kernel<<<BB * EE, 256>>>();
    // 3. out = residual
    copy_kernel<<<(BB * NN * DD / 4) / 256, 256>>>(residual, out);
    // 4. down-proj + relu
    down_kernel<<<dim3(KK / 64, BB * EE), 256>>>(x, Wd, bd);
    // 5. up-proj + residual-in-adapter + gated scatter-add
    up_kernel<<<dim3(DD / 128, KK / 64, BB * EE), 256, UP_SMEM_BYTES>>>(x, Wu, bu, out);
}

// round 17
// speedup vs baseline: 1.0023x; 1.0023x over previous
#include <cuda_runtime.h>

// Problem constants
#define BB 4
#define NN 4096
#define DD 2048
#define EE 8
#define KK 1024
#define RR 128

typedef unsigned long long ull;

// ---------------- device scratch (no allocations allowed) ----------------
__device__ float d_logits[BB * EE * NN];                 // [B,E,N] gate logits
__device__ int   d_idx[BB * EE * KK];                    // selected token indices
__device__ float d_g[BB * EE * KK];                      // gate values for selected
__device__ float d_H[(size_t)BB * EE * KK * RR];         // relu(down) activations

// ---------------- f32x2 helpers (FFMA2 path, PTX-only) ----------------
__device__ __forceinline__ ull pack2(float lo, float hi) {
    ull r;
    asm("mov.b64 %0, {%1, %2};" : "=l"(r) : "f"(lo), "f"(hi));
    return r;
}
__device__ __forceinline__ void unpack2(ull v, float& lo, float& hi) {
    asm("mov.b64 {%0, %1}, %2;" : "=f"(lo), "=f"(hi) : "l"(v));
}
__device__ __forceinline__ ull ffma2(ull a, ull b, ull c) {
    ull d;
    asm("fma.rn.f32x2 %0, %1, %2, %3;" : "=l"(d) : "l"(a), "l"(b), "l"(c));
    return d;
}
__device__ __forceinline__ void red_add_v2(float* p, float a, float b) {
    asm volatile("red.global.add.v2.f32 [%0], {%1, %2};"
                 :: "l"(p), "f"(a), "f"(b) : "memory");
}

// ---------------- 1. gating: logitsT[b,e,n] = x[b,n,:] @ Wg[:,e] + bg[e] ----------------
__global__ __launch_bounds__(256) void gate_kernel(const float* __restrict__ x,
                                                   const float* __restrict__ Wg,
                                                   const float* __restrict__ bg) {
    int gw   = (blockIdx.x * 256 + threadIdx.x) >> 5;   // token id in [0, B*N)
    int lane = threadIdx.x & 31;
    const float4* xr = (const float4*)(x + (size_t)gw * DD);

    float acc[EE];
#pragma unroll
    for (int e = 0; e < EE; e++) acc[e] = 0.f;

#pragma unroll 4
    for (int it = 0; it < DD / 128; ++it) {
        float4 xv = xr[it * 32 + lane];
        int d0 = (it * 32 + lane) * 4;
        const float4* wg4 = (const float4*)(Wg + (size_t)d0 * EE);
        float xs[4] = {xv.x, xv.y, xv.z, xv.w};
#pragma unroll
        for (int j = 0; j < 4; j++) {
            float4 w0 = wg4[2 * j];
            float4 w1 = wg4[2 * j + 1];
            acc[0] += xs[j] * w0.x; acc[1] += xs[j] * w0.y;
            acc[2] += xs[j] * w0.z; acc[3] += xs[j] * w0.w;
            acc[4] += xs[j] * w1.x; acc[5] += xs[j] * w1.y;
            acc[6] += xs[j] * w1.z; acc[7] += xs[j] * w1.w;
        }
    }
#pragma unroll
    for (int off = 16; off; off >>= 1) {
#pragma unroll
        for (int e = 0; e < EE; e++)
            acc[e] += __shfl_xor_sync(0xFFFFFFFFu, acc[e], off);
    }
    if (lane < EE) {
        float v = acc[0];
#pragma unroll
        for (int e = 1; e < EE; e++) if (lane == e) v = acc[e];
        int b = gw / NN, n = gw % NN;
        d_logits[(size_t)(b * EE + lane) * NN + n] = v + bg[lane];
    }
}

// ---------------- 2. top-K per (b,e): radix select on monotone uint keys ----------------
__global__ __launch_bounds__(256) void topk_kernel() {
    const int be = blockIdx.x;                     // 0..31
    __shared__ unsigned keys[NN];
    __shared__ unsigned hist[256];
    __shared__ unsigned sh_prefix, sh_remaining, sh_cnt;

    const float* lrow = d_logits + (size_t)be * NN;
    const int tid = threadIdx.x;

    for (int i = tid; i < NN; i += 256) {
        unsigned b = __float_as_uint(lrow[i]);
        keys[i] = (b & 0x80000000u) ? ~b : (b | 0x80000000u);
    }
    if (tid == 0) { sh_prefix = 0u; sh_remaining = KK; sh_cnt = 0u; }
    __syncthreads();

    for (int pass = 0; pass < 4; ++pass) {
        int shift = 24 - 8 * pass;
        for (int i = tid; i < 256; i += 256) hist[i] = 0u;
        __syncthreads();
        unsigned prefix = sh_prefix;
        unsigned remaining = sh_remaining;
        int hs = shift + 8;
        for (int i = tid; i < NN; i += 256) {
            unsigned key = keys[i];
            bool ok = (pass == 0) || ((key >> hs) == (prefix >> hs));
            if (ok) atomicAdd(&hist[(key >> shift) & 0xFFu], 1u);
        }
        __syncthreads();
        if (tid == 0) {
            unsigned cum = 0; int sel = 0;
            for (int v = 255; v >= 0; v--) {
                if (cum + hist[v] >= remaining) { sel = v; break; }
                cum += hist[v];
            }
            sh_prefix = prefix | ((unsigned)sel << shift);
            sh_remaining = remaining - cum;
        }
        __syncthreads();
    }

    unsigned T = sh_prefix;
    unsigned eqNeed = sh_remaining;

    // strictly-greater keys take arbitrary slots (scatter-add makes order irrelevant)
    for (int i = tid; i < NN; i += 256) {
        if (keys[i] > T) {
            unsigned p = atomicAdd(&sh_cnt, 1u);
            d_idx[be * KK + p] = i;
            d_g[be * KK + p]   = lrow[i];
        }
    }
    __syncthreads();
    // ties at the threshold: lowest indices first (matches jax stable top_k)
    if (tid == 0) {
        unsigned base = sh_cnt, taken = 0;
        for (int i = 0; i < NN && taken < eqNeed; i++) {
            if (keys[i] == T) {
                d_idx[be * KK + base + taken] = i;
                d_g[be * KK + base + taken]   = lrow[i];
                taken++;
            }
        }
    }
}

// ---------------- 3. out = residual ----------------
__global__ __launch_bounds__(256) void copy_kernel(const float* __restrict__ res,
                                                   float* __restrict__ out) {
    int i = blockIdx.x * 256 + threadIdx.x;     // float4 index
    ((float4*)out)[i] = ((const float4*)res)[i];
}

// ---------------- 4. down: H = relu(gather(x) @ Wd[e] + bd[e]) ----------------
// tile: 64 tokens x 128 (all of R), K-chunks of 32 over D. 256 thr, 4x4 f32x2 accs.
__global__ __launch_bounds__(256) void down_kernel(const float* __restrict__ x,
                                                   const float* __restrict__ Wd,
                                                   const float* __restrict__ bd) {
    const int mt = blockIdx.x;          // 0..15 token tile
    const int be = blockIdx.y;          // 0..31
    const int b = be >> 3, e = be & 7;

    __shared__ float Xs[64][36];        // [m][k], padded to keep 16B alignment
    __shared__ float Ws[32][128];       // [k][r]
    __shared__ int   tok[64];

    const int tid = threadIdx.x;
    if (tid < 64) tok[tid] = d_idx[be * KK + mt * 64 + tid];
    __syncthreads();

    const int tx = tid & 15, ty = tid >> 4;
    ull acc[4][4];
#pragma unroll
    for (int r = 0; r < 4; r++)
#pragma unroll
        for (int j = 0; j < 4; j++) acc[r][j] = 0ULL;

    const float* Wdp = Wd + (size_t)e * DD * RR;
    const int lr = tid >> 3;            // 0..31
    const int lc = (tid & 7) * 4;       // 0..28
    const float* xrow0 = x + ((size_t)(b * NN + tok[lr]) * DD + lc);
    const float* xrow1 = x + ((size_t)(b * NN + tok[lr + 32]) * DD + lc);

    for (int k0 = 0; k0 < DD; k0 += 32) {
        *(float4*)&Xs[lr][lc]      = *(const float4*)(xrow0 + k0);
        *(float4*)&Xs[lr + 32][lc] = *(const float4*)(xrow1 + k0);
        const float4* wsrc = (const float4*)(Wdp + (size_t)k0 * RR);
#pragma unroll
        for (int j = 0; j < 4; j++) {
            int f = tid + j * 256;
            ((float4*)Ws)[f] = wsrc[f];
        }
        __syncthreads();
#pragma unroll
        for (int k = 0; k < 32; k++) {
            ull a[4], wv[4];
#pragma unroll
            for (int r = 0; r < 4; r++) {
                float xv = Xs[ty * 4 + r][k];
                a[r] = pack2(xv, xv);
            }
#pragma unroll
            for (int j = 0; j < 4; j++)
                wv[j] = *(const ull*)&Ws[k][tx * 2 + 32 * j];
#pragma unroll
            for (int r = 0; r < 4; r++)
#pragma unroll
                for (int j = 0; j < 4; j++)
                    acc[r][j] = ffma2(a[r], wv[j], acc[r][j]);
        }
        __syncthreads();
    }

#pragma unroll
    for (int r = 0; r < 4; r++) {
        int slot = be * KK + mt * 64 + ty * 4 + r;
        float* hrow = d_H + (size_t)slot * RR;
#pragma unroll
        for (int j = 0; j < 4; j++) {
            int col = tx * 2 + 32 * j;
            float lo, hi; unpack2(acc[r][j], lo, hi);
            lo = fmaxf(lo + bd[e * RR + col], 0.f);
            hi = fmaxf(hi + bd[e * RR + col + 1], 0.f);
            *(float2*)(hrow + col) = make_float2(lo, hi);
        }
    }
}

// ---------------- 5. up + combine: out += g * (H @ Wu[e] + bu[e] + x_in) ----------------
// grid: (D/128 chunks, K/64 token tiles, B*E). One-shot smem load, 128 k-iters.
#define UP_SMEM_BYTES ((64 * 132 + 128 * 128 + 64 + 64) * 4)
__global__ __launch_bounds__(256) void up_kernel(const float* __restrict__ x,
                                                 const float* __restrict__ Wu,
                                                 const float* __restrict__ bu,
                                                 float* __restrict__ out) {
    extern __shared__ float sm[];
    float* Hs  = sm;                       // [64][132] (padded: banks)
    float* Ws  = sm + 64 * 132;            // [128][128]
    int*   tok = (int*)(Ws + 128 * 128);   // [64]
    float* gv  = (float*)(tok + 64);       // [64]

    const int dc = blockIdx.x, mt = blockIdx.y, be = blockIdx.z;
    const int b = be >> 3, e = be & 7;
    const int tid = threadIdx.x;
    const int tx = tid & 15, ty = tid >> 4;

    if (tid < 64) {
        tok[tid] = d_idx[be * KK + mt * 64 + tid];
        gv[tid]  = d_g[be * KK + mt * 64 + tid];
    }
    {   // load H tile [64][128]
        int r = tid >> 2;
        int c = (tid & 3) * 32;
        const float4* src = (const float4*)(d_H + ((size_t)(be * KK + mt * 64 + r) * RR + c));
        float4* dst = (float4*)&Hs[r * 132 + c];
#pragma unroll
        for (int j = 0; j < 8; j++) dst[j] = src[j];
    }
    {   // load Wu chunk [128][128]
        const float* wp = Wu + ((size_t)e * RR * DD + dc * 128);
#pragma unroll
        for (int j = 0; j < 16; j++) {
            int f = tid + j * 256;
            int kk = f >> 5, c4 = (f & 31) * 4;
            *(float4*)&Ws[kk * 128 + c4] = *(const float4*)(wp + (size_t)kk * DD + c4);
        }
    }
    __syncthreads();

    ull acc[4][4];
#pragma unroll
    for (int r = 0; r < 4; r++)
#pragma unroll
        for (int j = 0; j < 4; j++) acc[r][j] = 0ULL;

#pragma unroll 8
    for (int k = 0; k < RR; k++) {
        ull a[4], wv[4];
#pragma unroll
        for (int r = 0; r < 4; r++) {
            float hv = Hs[(ty * 4 + r) * 132 + k];
            a[r] = pack2(hv, hv);
        }
#pragma unroll
        for (int j = 0; j < 4; j++)
            wv[j] = *(const ull*)&Ws[k * 128 + tx * 2 + 32 * j];
#pragma unroll
        for (int r = 0; r < 4; r++)
#pragma unroll
            for (int j = 0; j < 4; j++)
                acc[r][j] = ffma2(a[r], wv[j], acc[r][j]);
    }

    const float* bue = bu + e * DD + dc * 128;
#pragma unroll
    for (int r = 0; r < 4; r++) {
        int rl = ty * 4 + r;
        int t  = tok[rl];
        float gg = gv[rl];
        float* orow       = out + ((size_t)(b * NN + t) * DD + dc * 128);
        const float* xrow = x   + ((size_t)(b * NN + t) * DD + dc * 128);
#pragma unroll
        for (int j = 0; j < 4; j++) {
            int col = tx * 2 + 32 * j;
            float lo, hi; unpack2(acc[r][j], lo, hi);
            float2 xin = *(const float2*)(xrow + col);
            lo = gg * (lo + bue[col]     + xin.x);
            hi = gg * (hi + bue[col + 1] + xin.y);
            red_add_v2(orow + col, lo, hi);
        }
    }
}

// ---------------- launch ----------------
extern "C" void kernel_launch(void* const* d_in, const int* in_sizes, int n_in,
                              void* d_out, int out_size) {
    const float* x        = (const float*)d_in[0];
    const float* residual = (const float*)d_in[1];
    const float* Wg       = (const float*)d_in[2];
    const float* bg       = (const float*)d_in[3];
    const float* Wd       = (const float*)d_in[4];
    const float* bd       = (const float*)d_in[5];
    const float* Wu       = (const float*)d_in[6];
    const float* bu       = (const float*)d_in[7];
    float* out = (float*)d_out;

    (void)in_sizes; (void)n_in; (void)out_size;

    cudaFuncSetAttribute(up_kernel, cudaFuncAttributeMaxDynamicSharedMemorySize,
                         UP_SMEM_BYTES);

    // 1. gating logits
    gate_kernel<<<(BB * NN) / 8, 256>>>(x, Wg, bg);
    // 2. top-K selection per (b,e)
    topk_kernel<<<BB * EE, 256>>>();
    // 3. out = residual
    copy_kernel<<<(BB * NN * DD / 4) / 256, 256>>>(residual, out);
    // 4. down-proj + relu
    down_kernel<<<dim3(KK / 64, BB * EE), 256>>>(x, Wd, bd);
    // 5. up-proj + residual-in-adapter + gated scatter-add
    up_kernel<<<dim3(DD / 128, KK / 64, BB * EE), 256, UP_SMEM_BYTES>>>(x, Wu, bu, out);
}